// round 1
// baseline (speedup 1.0000x reference)
#include <cuda_runtime.h>

#define Bb 2
#define Nn 2048
#define Ee 1024
#define Hh 16
#define Dd 64
#define BH (Bb*Hh)
#define ROWS (Bb*Nn)

// Scratch (no allocations allowed in kernel_launch)
__device__ float g_Q[BH * Nn * Dd];     // [B,H,N,D]
__device__ float g_K[BH * Nn * Dd];
__device__ float g_V[BH * Nn * Dd];
__device__ float g_ctx[ROWS * Ee];      // attention output repacked to [B,N,E]

// ---------------------------------------------------------------------------
// Tiled fp32 GEMM: C[M,NW] = A[M,1024] @ W[1024,NW] (+bias), BM=BN=64, BK=16,
// 256 threads, 4x4 microtile with float4 smem reads.
// QKV=true: A = x, epilogue scatters into g_Q/g_K/g_V ([B,H,N,D] layout).
// QKV=false: A = g_ctx, epilogue writes C with bias to Cout.
// ---------------------------------------------------------------------------
template<int NW, bool QKV>
__global__ __launch_bounds__(256)
void gemm_kernel(const float* __restrict__ A, const float* __restrict__ W,
                 const float* __restrict__ bias, float* __restrict__ Cout)
{
    constexpr int K = Ee;
    __shared__ float As[16][64];
    __shared__ float Bs[16][64];

    const int tid = threadIdx.x;
    const int tx = tid & 15;         // 0..15 (N direction)
    const int ty = tid >> 4;         // 0..15 (M direction)
    const int m0 = blockIdx.y * 64;
    const int n0 = blockIdx.x * 64;

    const float* Ap = QKV ? A : g_ctx;

    // load indices
    const int arow = tid >> 2;           // 0..63
    const int akc  = (tid & 3) * 4;      // 0,4,8,12
    const int brow = tid >> 4;           // 0..15
    const int bcol = (tid & 15) * 4;     // 0..60

    float c[4][4] = {};

    for (int k0 = 0; k0 < K; k0 += 16) {
        float4 av = *(const float4*)&Ap[(size_t)(m0 + arow) * K + k0 + akc];
        float4 bv = *(const float4*)&W[(size_t)(k0 + brow) * NW + n0 + bcol];
        __syncthreads();   // previous compute done before smem overwrite
        As[akc + 0][arow] = av.x;
        As[akc + 1][arow] = av.y;
        As[akc + 2][arow] = av.z;
        As[akc + 3][arow] = av.w;
        *(float4*)&Bs[brow][bcol] = bv;
        __syncthreads();
        #pragma unroll
        for (int k = 0; k < 16; ++k) {
            float4 a4 = *(const float4*)&As[k][ty * 4];
            float4 b4 = *(const float4*)&Bs[k][tx * 4];
            float a[4] = {a4.x, a4.y, a4.z, a4.w};
            float b[4] = {b4.x, b4.y, b4.z, b4.w};
            #pragma unroll
            for (int i = 0; i < 4; ++i)
                #pragma unroll
                for (int j = 0; j < 4; ++j)
                    c[i][j] += a[i] * b[j];
        }
    }

    if (QKV) {
        // column block n0+tx*4 .. +3 lies within one (s,h) 64-block
        const int c0  = n0 + tx * 4;
        const int s   = c0 >> 10;          // 0=Q,1=K,2=V
        const int rem = c0 & 1023;
        const int h   = rem >> 6;
        const int d0  = rem & 63;
        float* base = (s == 0) ? g_Q : (s == 1) ? g_K : g_V;
        const float4 bval = *(const float4*)&bias[c0];
        #pragma unroll
        for (int i = 0; i < 4; ++i) {
            const int m = m0 + ty * 4 + i;
            const int b = m >> 11;          // / 2048
            const int n = m & 2047;
            float4 o;
            o.x = c[i][0] + bval.x;
            o.y = c[i][1] + bval.y;
            o.z = c[i][2] + bval.z;
            o.w = c[i][3] + bval.w;
            *(float4*)&base[(((size_t)(b * Hh + h) * Nn + n) * Dd) + d0] = o;
        }
    } else {
        const float4 bval = *(const float4*)&bias[n0 + tx * 4];
        #pragma unroll
        for (int i = 0; i < 4; ++i) {
            const int m = m0 + ty * 4 + i;
            float4 o;
            o.x = c[i][0] + bval.x;
            o.y = c[i][1] + bval.y;
            o.z = c[i][2] + bval.z;
            o.w = c[i][3] + bval.w;
            *(float4*)&Cout[(size_t)m * NW + n0 + tx * 4] = o;
        }
    }
}

// ---------------------------------------------------------------------------
// Flash attention (fp32, online softmax). One query row per thread,
// 128 rows per block, KV tiles of 64 rows staged in smem.
// Output written directly into g_ctx in [B,N,E] layout for the proj GEMM.
// ---------------------------------------------------------------------------
__global__ __launch_bounds__(128)
void attn_kernel()
{
    __shared__ float Ks[64][Dd];
    __shared__ float Vs[64][Dd];

    const int bh  = blockIdx.y;                 // 0..31
    const int tid = threadIdx.x;                // 0..127
    const int row = blockIdx.x * 128 + tid;     // 0..2047

    const float* Qb = g_Q + (size_t)bh * Nn * Dd;
    const float* Kb = g_K + (size_t)bh * Nn * Dd;
    const float* Vb = g_V + (size_t)bh * Nn * Dd;

    // q row pre-scaled by 1/sqrt(D)
    float q[Dd];
    #pragma unroll
    for (int d = 0; d < Dd; d += 4) {
        float4 v = *(const float4*)&Qb[(size_t)row * Dd + d];
        q[d + 0] = v.x * 0.125f;
        q[d + 1] = v.y * 0.125f;
        q[d + 2] = v.z * 0.125f;
        q[d + 3] = v.w * 0.125f;
    }

    float acc[Dd] = {};
    float mrun = -1e30f, lrun = 0.f;

    for (int t0 = 0; t0 < Nn; t0 += 64) {
        __syncthreads();
        #pragma unroll
        for (int i = 0; i < 8; ++i) {
            const int idx = (tid + i * 128) * 4;    // 0..4092
            const int r = idx >> 6;
            const int cc = idx & 63;
            *(float4*)&Ks[r][cc] = *(const float4*)&Kb[(size_t)(t0 + r) * Dd + cc];
            *(float4*)&Vs[r][cc] = *(const float4*)&Vb[(size_t)(t0 + r) * Dd + cc];
        }
        __syncthreads();

        #pragma unroll 1
        for (int j0 = 0; j0 < 64; j0 += 16) {
            float s[16];
            float mloc = -1e30f;
            #pragma unroll
            for (int jj = 0; jj < 16; ++jj) {
                float acc_s = 0.f;
                #pragma unroll
                for (int d = 0; d < Dd; ++d)
                    acc_s += q[d] * Ks[j0 + jj][d];
                s[jj] = acc_s;
                mloc = fmaxf(mloc, acc_s);
            }
            const float mnew = fmaxf(mrun, mloc);
            const float corr = __expf(mrun - mnew);
            lrun *= corr;
            #pragma unroll
            for (int d = 0; d < Dd; ++d)
                acc[d] *= corr;
            #pragma unroll
            for (int jj = 0; jj < 16; ++jj) {
                const float p = __expf(s[jj] - mnew);
                lrun += p;
                #pragma unroll
                for (int d = 0; d < Dd; ++d)
                    acc[d] += p * Vs[j0 + jj][d];
            }
            mrun = mnew;
        }
    }

    const float inv = 1.f / lrun;
    const int b = bh >> 4;      // / Hh
    const int h = bh & 15;
    float* dst = g_ctx + ((size_t)(b * Nn + row) * Ee) + h * Dd;
    #pragma unroll
    for (int d = 0; d < Dd; d += 4) {
        float4 o;
        o.x = acc[d + 0] * inv;
        o.y = acc[d + 1] * inv;
        o.z = acc[d + 2] * inv;
        o.w = acc[d + 3] * inv;
        *(float4*)&dst[d] = o;
    }
}

// ---------------------------------------------------------------------------
extern "C" void kernel_launch(void* const* d_in, const int* in_sizes, int n_in,
                              void* d_out, int out_size)
{
    const float* x      = (const float*)d_in[0];
    const float* w_qkv  = (const float*)d_in[1];
    const float* b_qkv  = (const float*)d_in[2];
    const float* w_proj = (const float*)d_in[3];
    const float* b_proj = (const float*)d_in[4];
    float* out = (float*)d_out;

    // 1) QKV GEMM + scatter into [B,H,N,D] Q/K/V
    gemm_kernel<3 * Ee, true><<<dim3((3 * Ee) / 64, ROWS / 64), 256>>>(x, w_qkv, b_qkv, nullptr);
    // 2) Flash attention -> g_ctx [B,N,E]
    attn_kernel<<<dim3(Nn / 128, BH), 128>>>();
    // 3) Projection GEMM -> out
    gemm_kernel<Ee, false><<<dim3(Ee / 64, ROWS / 64), 256>>>(x /*unused*/, w_proj, b_proj, out);
}

// round 5
// speedup vs baseline: 1.0302x; 1.0302x over previous
#include <cuda_runtime.h>
#include <cuda_bf16.h>
#include <cstdint>

#define Bb 2
#define Nn 2048
#define Ee 1024
#define Hh 16
#define Dd 64
#define BH (Bb*Hh)
#define ROWS (Bb*Nn)

// ---------------------------------------------------------------------------
// Scratch (exactly the R1-proven set)
// ---------------------------------------------------------------------------
__device__ float g_Q[BH * Nn * Dd];     // [B,H,N,D]
__device__ float g_K[BH * Nn * Dd];
__device__ float g_V[BH * Nn * Dd];
__device__ float g_ctx[ROWS * Ee];      // attention output, [B,N,E]

// ---------------------------------------------------------------------------
// helpers
// ---------------------------------------------------------------------------
__device__ __forceinline__ void mma_bf16(float* c, const uint32_t* a, const uint32_t* b) {
    asm volatile(
        "mma.sync.aligned.m16n8k16.row.col.f32.bf16.bf16.f32 "
        "{%0,%1,%2,%3}, {%4,%5,%6,%7}, {%8,%9}, {%0,%1,%2,%3};"
        : "+f"(c[0]), "+f"(c[1]), "+f"(c[2]), "+f"(c[3])
        : "r"(a[0]), "r"(a[1]), "r"(a[2]), "r"(a[3]), "r"(b[0]), "r"(b[1]));
}

// FMA-pipe exp (keeps MUFU free). Accurate to ~3e-7 rel on [-87, 0].
__device__ __forceinline__ float fexp(float x) {
    float y = fmaxf(x * 1.4426950408889634f, -120.f);
    float n = floorf(y);
    float f = y - n;
    float p = 1.5403530451e-4f;
    p = fmaf(p, f, 1.3333558146e-3f);
    p = fmaf(p, f, 9.6181291076e-3f);
    p = fmaf(p, f, 5.5504108664e-2f);
    p = fmaf(p, f, 2.4022650695e-1f);
    p = fmaf(p, f, 6.9314718056e-1f);
    p = fmaf(p, f, 1.0f);
    return __int_as_float(__float_as_int(p) + (((int)n) << 23));
}

// ---------------------------------------------------------------------------
// HMMA GEMM with inline fp32->bf16(hi/lo) conversion.
// C[4096, NW] = A[4096,1024] @ W[1024, NW] (+bias)
// bf16-split: AhBh + AhBl + AlBh, fp32 accum (rel err ~1e-5).
// BM=BN=128, BK=16, 256 threads (8 warps as 2m x 4n), ~24 KB static smem.
// MODE 0: A = x, epilogue scatters Q/K/V ([B,H,N,D]).  MODE 1: A = g_ctx -> Cout.
// ---------------------------------------------------------------------------
template<int NW, int MODE>
__global__ __launch_bounds__(256)
void hmma_gemm(const float* __restrict__ Ain, const float* __restrict__ W,
               const float* __restrict__ bias, float* __restrict__ Cout)
{
    // padded stride 24 bf16 (48 B): fragment reads are bank-conflict-free
    __shared__ __nv_bfloat16 Ah[128][24], Al[128][24];
    __shared__ __nv_bfloat16 Bh[128][24], Bl[128][24];   // [n][k]

    const int tid  = threadIdx.x;
    const int lane = tid & 31;
    const int wid  = tid >> 5;
    const int gid  = lane >> 2;      // 0..7
    const int tig  = lane & 3;       // 0..3
    const int wm   = wid & 1;        // 2 warps in M
    const int wn   = wid >> 1;       // 4 warps in N

    const int m0 = blockIdx.y * 128;
    const int n0 = blockIdx.x * 128;

    const float* A = (MODE == 0) ? Ain : g_ctx;

    // global->smem load mapping
    const int a_row = tid >> 1;          // 0..127
    const int a_k   = (tid & 1) * 8;     // 0 or 8
    const int b_k   = tid >> 4;          // 0..15
    const int b_n   = (tid & 15) * 8;    // 0..120

    float acc[4][4][4] = {};

    #pragma unroll 1
    for (int c = 0; c < 64; ++c) {
        const int k0 = c * 16;
        __syncthreads();   // previous compute done before smem overwrite

        // ---- A tile: 128x16 fp32 -> bf16 hi/lo ----
        #pragma unroll
        for (int q = 0; q < 2; ++q) {
            const float4 v = *(const float4*)&A[(size_t)(m0 + a_row) * Ee + k0 + a_k + q * 4];
            const float vv[4] = {v.x, v.y, v.z, v.w};
            __nv_bfloat16 h[4], l[4];
            #pragma unroll
            for (int j = 0; j < 4; ++j) {
                h[j] = __float2bfloat16(vv[j]);
                l[j] = __float2bfloat16(vv[j] - __bfloat162float(h[j]));
            }
            const int kk = a_k + q * 4;
            *(__nv_bfloat162*)&Ah[a_row][kk]     = __nv_bfloat162(h[0], h[1]);
            *(__nv_bfloat162*)&Ah[a_row][kk + 2] = __nv_bfloat162(h[2], h[3]);
            *(__nv_bfloat162*)&Al[a_row][kk]     = __nv_bfloat162(l[0], l[1]);
            *(__nv_bfloat162*)&Al[a_row][kk + 2] = __nv_bfloat162(l[2], l[3]);
        }

        // ---- B tile: W[k0..k0+15][n0..n0+127] -> Bs[n][k] (transposed) ----
        #pragma unroll
        for (int q = 0; q < 2; ++q) {
            const float4 v = *(const float4*)&W[(size_t)(k0 + b_k) * NW + n0 + b_n + q * 4];
            const float vv[4] = {v.x, v.y, v.z, v.w};
            #pragma unroll
            for (int j = 0; j < 4; ++j) {
                const __nv_bfloat16 h = __float2bfloat16(vv[j]);
                const int nn = b_n + q * 4 + j;
                Bh[nn][b_k] = h;
                Bl[nn][b_k] = __float2bfloat16(vv[j] - __bfloat162float(h));
            }
        }
        __syncthreads();

        // ---- fragments + 3-pass MMA ----
        uint32_t af[4][4], bhf[4][2], blf[4][2];
        #pragma unroll
        for (int mt = 0; mt < 4; ++mt) {
            const int r = wm * 64 + mt * 16 + gid;
            af[mt][0] = *(const uint32_t*)&Ah[r][2 * tig];
            af[mt][1] = *(const uint32_t*)&Ah[r + 8][2 * tig];
            af[mt][2] = *(const uint32_t*)&Ah[r][2 * tig + 8];
            af[mt][3] = *(const uint32_t*)&Ah[r + 8][2 * tig + 8];
        }
        #pragma unroll
        for (int nt = 0; nt < 4; ++nt) {
            const int rn = wn * 32 + nt * 8 + gid;
            bhf[nt][0] = *(const uint32_t*)&Bh[rn][2 * tig];
            bhf[nt][1] = *(const uint32_t*)&Bh[rn][2 * tig + 8];
            blf[nt][0] = *(const uint32_t*)&Bl[rn][2 * tig];
            blf[nt][1] = *(const uint32_t*)&Bl[rn][2 * tig + 8];
        }
        #pragma unroll
        for (int mt = 0; mt < 4; ++mt)
            #pragma unroll
            for (int nt = 0; nt < 4; ++nt)
                mma_bf16(acc[mt][nt], af[mt], bhf[nt]);
        #pragma unroll
        for (int mt = 0; mt < 4; ++mt)
            #pragma unroll
            for (int nt = 0; nt < 4; ++nt)
                mma_bf16(acc[mt][nt], af[mt], blf[nt]);
        // reload af <- A-lo
        #pragma unroll
        for (int mt = 0; mt < 4; ++mt) {
            const int r = wm * 64 + mt * 16 + gid;
            af[mt][0] = *(const uint32_t*)&Al[r][2 * tig];
            af[mt][1] = *(const uint32_t*)&Al[r + 8][2 * tig];
            af[mt][2] = *(const uint32_t*)&Al[r][2 * tig + 8];
            af[mt][3] = *(const uint32_t*)&Al[r + 8][2 * tig + 8];
        }
        #pragma unroll
        for (int mt = 0; mt < 4; ++mt)
            #pragma unroll
            for (int nt = 0; nt < 4; ++nt)
                mma_bf16(acc[mt][nt], af[mt], bhf[nt]);
    }

    // ---- epilogue ----
    #pragma unroll
    for (int mt = 0; mt < 4; ++mt) {
        #pragma unroll
        for (int hrow = 0; hrow < 2; ++hrow) {
            const int m = m0 + wm * 64 + mt * 16 + hrow * 8 + gid;
            #pragma unroll
            for (int nt = 0; nt < 4; ++nt) {
                const int c0 = n0 + wn * 32 + nt * 8 + tig * 2;
                const float r0 = acc[mt][nt][hrow * 2 + 0] + bias[c0];
                const float r1 = acc[mt][nt][hrow * 2 + 1] + bias[c0 + 1];
                if (MODE == 0) {
                    const int sel = c0 >> 10;          // 0=Q,1=K,2=V
                    const int rem = c0 & 1023;
                    const int h = rem >> 6;
                    const int d0 = rem & 63;
                    float* base = (sel == 0) ? g_Q : (sel == 1) ? g_K : g_V;
                    const int b = m >> 11;
                    const int n = m & 2047;
                    float2 o = {r0, r1};
                    *(float2*)&base[(((size_t)(b * Hh + h) * Nn + n) * Dd) + d0] = o;
                } else {
                    float2 o = {r0, r1};
                    *(float2*)&Cout[(size_t)m * NW + c0] = o;
                }
            }
        }
    }
}

// ---------------------------------------------------------------------------
// Flash attention — R1-proven kernel, fp32 ctx epilogue, fexp instead of __expf
// ---------------------------------------------------------------------------
__global__ __launch_bounds__(128)
void attn_kernel()
{
    __shared__ float Ks[64][Dd];
    __shared__ float Vs[64][Dd];

    const int bh  = blockIdx.y;
    const int tid = threadIdx.x;
    const int row = blockIdx.x * 128 + tid;

    const float* Qb = g_Q + (size_t)bh * Nn * Dd;
    const float* Kb = g_K + (size_t)bh * Nn * Dd;
    const float* Vb = g_V + (size_t)bh * Nn * Dd;

    float q[Dd];
    #pragma unroll
    for (int d = 0; d < Dd; d += 4) {
        float4 v = *(const float4*)&Qb[(size_t)row * Dd + d];
        q[d + 0] = v.x * 0.125f;
        q[d + 1] = v.y * 0.125f;
        q[d + 2] = v.z * 0.125f;
        q[d + 3] = v.w * 0.125f;
    }

    float acc[Dd] = {};
    float mrun = -1e30f, lrun = 0.f;

    for (int t0 = 0; t0 < Nn; t0 += 64) {
        __syncthreads();
        #pragma unroll
        for (int i = 0; i < 8; ++i) {
            const int idx = (tid + i * 128) * 4;
            const int r = idx >> 6;
            const int cc = idx & 63;
            *(float4*)&Ks[r][cc] = *(const float4*)&Kb[(size_t)(t0 + r) * Dd + cc];
            *(float4*)&Vs[r][cc] = *(const float4*)&Vb[(size_t)(t0 + r) * Dd + cc];
        }
        __syncthreads();

        #pragma unroll 1
        for (int j0 = 0; j0 < 64; j0 += 16) {
            float s[16];
            float mloc = -1e30f;
            #pragma unroll
            for (int jj = 0; jj < 16; ++jj) {
                float a = 0.f;
                #pragma unroll
                for (int d = 0; d < Dd; ++d)
                    a += q[d] * Ks[j0 + jj][d];
                s[jj] = a;
                mloc = fmaxf(mloc, a);
            }
            const float mnew = fmaxf(mrun, mloc);
            const float corr = fexp(mrun - mnew);
            lrun *= corr;
            #pragma unroll
            for (int d = 0; d < Dd; ++d)
                acc[d] *= corr;
            #pragma unroll
            for (int jj = 0; jj < 16; ++jj) {
                const float p = fexp(s[jj] - mnew);
                lrun += p;
                #pragma unroll
                for (int d = 0; d < Dd; ++d)
                    acc[d] += p * Vs[j0 + jj][d];
            }
            mrun = mnew;
        }
    }

    const float inv = 1.f / lrun;
    const int b = bh >> 4;
    const int h = bh & 15;
    float* dst = g_ctx + ((size_t)(b * Nn + row) * Ee) + h * Dd;
    #pragma unroll
    for (int d = 0; d < Dd; d += 4) {
        float4 o;
        o.x = acc[d + 0] * inv;
        o.y = acc[d + 1] * inv;
        o.z = acc[d + 2] * inv;
        o.w = acc[d + 3] * inv;
        *(float4*)&dst[d] = o;
    }
}

// ---------------------------------------------------------------------------
extern "C" void kernel_launch(void* const* d_in, const int* in_sizes, int n_in,
                              void* d_out, int out_size)
{
    const float* x      = (const float*)d_in[0];
    const float* w_qkv  = (const float*)d_in[1];
    const float* b_qkv  = (const float*)d_in[2];
    const float* w_proj = (const float*)d_in[3];
    const float* b_proj = (const float*)d_in[4];
    float* out = (float*)d_out;

    // 1) QKV GEMM (HMMA, inline bf16 split) + scatter into [B,H,N,D]
    hmma_gemm<3 * Ee, 0><<<dim3(3 * Ee / 128, ROWS / 128), 256>>>(x, w_qkv, b_qkv, nullptr);
    // 2) Flash attention -> g_ctx [B,N,E] (fp32)
    attn_kernel<<<dim3(Nn / 128, BH), 128>>>();
    // 3) Projection GEMM (HMMA) -> out
    hmma_gemm<Ee, 1><<<dim3(Ee / 128, ROWS / 128), 256>>>(nullptr, w_proj, b_proj, out);
}